// round 16
// baseline (speedup 1.0000x reference)
#include <cuda_runtime.h>
#include <cuda_fp16.h>
#include <math.h>
#include <stdint.h>

#define NN 30000
#define TT 4
#define FIN 256
#define HH 64
#define HEADS 4
#define DD 256
#define EE 240000
#define ETOT 270000            // EE + NN self loops
#define NEG_SLOPE 0.2f
#define NB_SCAN 118            // ceil(NN/256)
#define ESZ (TT * NN * HEADS)

// ---------------- scratch (device globals: allocation-free) ----------------
__device__ __align__(16) float  g_h0[TT * NN * HH];     // xWp output (incl bp), (t,n) order
__device__ __align__(16) __half g_hph[TT * NN * DD];    // per-layer hp = h @ W  (fp16)
__device__ __align__(16) __half g_bufAh[TT * NN * DD];  // layer0 output (post ELU, fp16)
__device__ __align__(16) __half g_bufBh[TT * NN * DD];  // layer1 output (embs, fp16)
__device__ __align__(16) float  g_esed[2 * ESZ];        // es at 0, ed at ESZ
__device__ __align__(16) float  g_colsum[TT * DD];
__device__ float g_attn[TT];
// fp16 transposed weights: Wt[c][k] = W[k][c]
__device__ __align__(16) __half g_Wpt[HH * FIN];        // [64][256]
__device__ __align__(16) __half g_W0t[DD * HH];         // [256][64]
__device__ __align__(16) __half g_W1t[DD * DD];
__device__ __align__(16) __half g_Wvt[DD * DD];
// CSR
__device__ int g_deg[NN];
__device__ int g_off[NN];
__device__ int g_cursor[NN];
__device__ int g_part[256];
__device__ int g_srcs[ETOT];

// ---------------- utility ----------------
__global__ void zero_kernel(float4* __restrict__ p, int n4) {
    int i = blockIdx.x * blockDim.x + threadIdx.x;
    if (i < n4) p[i] = make_float4(0.f, 0.f, 0.f, 0.f);
}

__device__ __forceinline__ float eluf(float x) { return x > 0.f ? x : expm1f(x); }

// fp16 HMMA m16n8k16, fp32 accumulate. fp16 mantissa == tf32 mantissa (10 bits),
// so precision matches the tf32 path (measured 2.6-2.8e-4) while doubling MMA rate.
__device__ __forceinline__ void mma_f16(float* c, const uint32_t* a, const uint32_t* b) {
    asm volatile(
        "mma.sync.aligned.m16n8k16.row.col.f32.f16.f16.f32 "
        "{%0,%1,%2,%3}, {%4,%5,%6,%7}, {%8,%9}, {%0,%1,%2,%3};"
        : "+f"(c[0]), "+f"(c[1]), "+f"(c[2]), "+f"(c[3])
        : "r"(a[0]), "r"(a[1]), "r"(a[2]), "r"(a[3]), "r"(b[0]), "r"(b[1]));
}

// ---------------- weight prep: fp16 transpose Wt[c][k] = W[k][c] ----------------
__global__ void wprep_kernel(const float* __restrict__ Wp, const float* __restrict__ W0,
                             const float* __restrict__ W1, const float* __restrict__ Wv)
{
    int idx = blockIdx.x * 256 + threadIdx.x;
    if (idx < FIN * HH) {                       // Wp: [256][64] -> Wpt[64][256]
        int k = idx / HH, c = idx % HH;
        g_Wpt[c * FIN + k] = __float2half(Wp[idx]);
        return;
    }
    idx -= FIN * HH;
    if (idx < HH * DD) {                        // W0: [64][256] -> W0t[256][64]
        int k = idx / DD, c = idx % DD;
        g_W0t[c * HH + k] = __float2half(W0[idx]);
        return;
    }
    idx -= HH * DD;
    if (idx < DD * DD) {                        // W1
        int k = idx / DD, c = idx % DD;
        g_W1t[c * DD + k] = __float2half(W1[idx]);
        return;
    }
    idx -= DD * DD;
    if (idx < DD * DD) {                        // Wv
        int k = idx / DD, c = idx % DD;
        g_Wvt[c * DD + k] = __float2half(Wv[idx]);
    }
}

// ---------------- CSR build ----------------
__global__ void hist_kernel(const int* __restrict__ ei) {
    int e = blockIdx.x * 256 + threadIdx.x;
    if (e >= ETOT) return;
    int d = (e < EE) ? ei[EE + e] : (e - EE);
    atomicAdd(&g_deg[d], 1);
}

__global__ void scan1_kernel() {
    __shared__ int sh[256];
    int tid = threadIdx.x;
    int i = blockIdx.x * 256 + tid;
    int v = (i < NN) ? g_deg[i] : 0;
    sh[tid] = v;
    __syncthreads();
#pragma unroll
    for (int off = 1; off < 256; off <<= 1) {
        int t = (tid >= off) ? sh[tid - off] : 0;
        __syncthreads();
        sh[tid] += t;
        __syncthreads();
    }
    if (i < NN) g_off[i] = sh[tid] - v;       // exclusive (local)
    if (tid == 255) g_part[blockIdx.x] = sh[255];
}

__global__ void scan2_kernel() {
    __shared__ int sh[256];
    int tid = threadIdx.x;
    int v = (tid < NB_SCAN) ? g_part[tid] : 0;
    sh[tid] = v;
    __syncthreads();
#pragma unroll
    for (int off = 1; off < 256; off <<= 1) {
        int t = (tid >= off) ? sh[tid - off] : 0;
        __syncthreads();
        sh[tid] += t;
        __syncthreads();
    }
    if (tid < NB_SCAN) g_part[tid] = sh[tid] - v;  // exclusive
}

__global__ void scan3_kernel() {
    int i = blockIdx.x * 256 + threadIdx.x;
    if (i < NN) {
        int o = g_off[i] + g_part[blockIdx.x];
        g_off[i] = o;
        g_cursor[i] = o;
    }
}

__global__ void scatter_kernel(const int* __restrict__ ei) {
    int e = blockIdx.x * 256 + threadIdx.x;
    if (e >= ETOT) return;
    int s, d;
    if (e < EE) { s = ei[e]; d = ei[EE + e]; }
    else        { s = e - EE; d = s; }
    int pos = atomicAdd(&g_cursor[d], 1);
    g_srcs[pos] = s;
}

// ---------------- fp16 tensor-core GEMM, double-buffered, fused esed / blend ----------------
// C(R x Nc) = A(R x K) @ B(K x Nc) (+bias). 128x128 tile, KTILE=16, 256 threads.
// Bt is half, pre-transposed [Ncols][K]. K multiple of 16.
// permT!=0: output row r=(n*permT+t) -> t*permN+n.
// asrc/adst != null: per-head dots of the BIASED output row -> g_esed (pre-zeroed).
// BLEND (requires AHALF): A row r = sum_t g_attn[t] * A[t*SLAB + r*K + k].
// AHALF: A is __half*.  HALFC: C is __half*.
template<int BLEND, int AHALF, int HALFC>
__global__ void __launch_bounds__(256) gemm_f16(
    const void* __restrict__ Av, const __half* __restrict__ Bt,
    const float* __restrict__ bias, void* __restrict__ Cv,
    int Rows, int K, int Ncols, int permT, int permN,
    const float* __restrict__ asrc, const float* __restrict__ adst)
{
    __shared__ __half Ash[2][128][24];   // [row][k], 16 used + 8 pad -> frag word row*12+t4, conflict-free
    __shared__ __half Bsh[2][128][24];   // [col][k]
    const int tid = threadIdx.x;
    const int wid = tid >> 5;
    const int lane = tid & 31;
    const int wm = wid >> 2;        // 0..1
    const int wn = wid & 3;         // 0..3
    const int g = lane >> 2;        // 0..7
    const int t4 = lane & 3;        // 0..3
    const int rowBase = blockIdx.y << 7;
    const int colBase = blockIdx.x << 7;

    const int arow = tid >> 1;            // 0..127 (also B col index)
    const int ak8 = (tid & 1) << 3;       // 0 / 8

    float acc[4][4][4];
#pragma unroll
    for (int mi = 0; mi < 4; mi++)
#pragma unroll
        for (int ni = 0; ni < 4; ni++)
#pragma unroll
            for (int q = 0; q < 4; q++) acc[mi][ni][q] = 0.f;

    const int gr = rowBase + arow;
    const bool aOK = gr < Rows;
    const size_t aoff = (size_t)(aOK ? gr : 0) * K + ak8;
    const float*  Apf = (const float*)Av + aoff;
    const __half* Aph = (const __half*)Av + aoff;
    const int gcol = colBase + arow;
    const bool bcOK = gcol < Ncols;
    const __half* Btp = Bt + (size_t)(bcOK ? gcol : 0) * K + ak8;
    const size_t SLAB = (size_t)NN * DD;

    float atw[4] = {0.f, 0.f, 0.f, 0.f};
    if (BLEND) { atw[0] = g_attn[0]; atw[1] = g_attn[1]; atw[2] = g_attn[2]; atw[3] = g_attn[3]; }

    const int nk = K >> 4;
    __half2 rah[4];
    uint4 rbh;

    auto load_tile = [&](int kt) {
        const int kb = kt << 4;
        if (AHALF && !BLEND) {
            uint4 q = make_uint4(0u, 0u, 0u, 0u);
            if (aOK) q = __ldg((const uint4*)(Aph + kb));
            *(uint4*)rah = q;
        } else if (AHALF && BLEND) {
            float v[8];
#pragma unroll
            for (int i = 0; i < 8; i++) v[i] = 0.f;
            if (aOK) {
#pragma unroll
                for (int s = 0; s < 4; s++) {
                    uint4 q = __ldg((const uint4*)(Aph + kb + s * SLAB));
                    float2 f0 = __half22float2(*reinterpret_cast<const __half2*>(&q.x));
                    float2 f1 = __half22float2(*reinterpret_cast<const __half2*>(&q.y));
                    float2 f2 = __half22float2(*reinterpret_cast<const __half2*>(&q.z));
                    float2 f3 = __half22float2(*reinterpret_cast<const __half2*>(&q.w));
                    v[0] += atw[s] * f0.x; v[1] += atw[s] * f0.y;
                    v[2] += atw[s] * f1.x; v[3] += atw[s] * f1.y;
                    v[4] += atw[s] * f2.x; v[5] += atw[s] * f2.y;
                    v[6] += atw[s] * f3.x; v[7] += atw[s] * f3.y;
                }
            }
            rah[0] = __floats2half2_rn(v[0], v[1]);
            rah[1] = __floats2half2_rn(v[2], v[3]);
            rah[2] = __floats2half2_rn(v[4], v[5]);
            rah[3] = __floats2half2_rn(v[6], v[7]);
        } else {
            float4 u0 = make_float4(0.f, 0.f, 0.f, 0.f);
            float4 u1 = u0;
            if (aOK) {
                u0 = *(const float4*)(Apf + kb);
                u1 = *(const float4*)(Apf + kb + 4);
            }
            rah[0] = __floats2half2_rn(u0.x, u0.y);
            rah[1] = __floats2half2_rn(u0.z, u0.w);
            rah[2] = __floats2half2_rn(u1.x, u1.y);
            rah[3] = __floats2half2_rn(u1.z, u1.w);
        }
        rbh = make_uint4(0u, 0u, 0u, 0u);
        if (bcOK) rbh = __ldg((const uint4*)(Btp + kb));
    };
    auto store_tile = [&](int buf) {
        *(uint4*)&Ash[buf][arow][ak8] = *(const uint4*)rah;
        *(uint4*)&Bsh[buf][arow][ak8] = rbh;
    };

    load_tile(0);
    store_tile(0);
    __syncthreads();

    for (int kt = 0; kt < nk; kt++) {
        const int buf = kt & 1;
        if (kt + 1 < nk) load_tile(kt + 1);
        const uint32_t* A32 = (const uint32_t*)&Ash[buf][0][0];
        const uint32_t* B32 = (const uint32_t*)&Bsh[buf][0][0];
        uint32_t afr[4][4];
        uint32_t bfr[4][2];
#pragma unroll
        for (int mi = 0; mi < 4; mi++) {
            int row = (wm << 6) + (mi << 4) + g;
            afr[mi][0] = A32[row * 12 + t4];
            afr[mi][1] = A32[(row + 8) * 12 + t4];
            afr[mi][2] = A32[row * 12 + t4 + 4];
            afr[mi][3] = A32[(row + 8) * 12 + t4 + 4];
        }
#pragma unroll
        for (int ni = 0; ni < 4; ni++) {
            int col = (wn << 5) + (ni << 3) + g;
            bfr[ni][0] = B32[col * 12 + t4];
            bfr[ni][1] = B32[col * 12 + t4 + 4];
        }
#pragma unroll
        for (int mi = 0; mi < 4; mi++)
#pragma unroll
            for (int ni = 0; ni < 4; ni++)
                mma_f16(acc[mi][ni], afr[mi], bfr[ni]);
        if (kt + 1 < nk) {
            store_tile(buf ^ 1);
            __syncthreads();
        }
    }

    // ---- epilogue: bias -> C value, store C (fp32 or fp16), fused es/ed dots ----
#pragma unroll
    for (int mi = 0; mi < 4; mi++) {
        int row0 = rowBase + (wm << 6) + (mi << 4) + g;
        int row1 = row0 + 8;
        int orow0 = -1, orow1 = -1;
        if (row0 < Rows) orow0 = permT ? ((row0 % permT) * permN + row0 / permT) : row0;
        if (row1 < Rows) orow1 = permT ? ((row1 % permT) * permN + row1 / permT) : row1;
        float es0 = 0.f, es1 = 0.f, ed0 = 0.f, ed1 = 0.f;
#pragma unroll
        for (int ni = 0; ni < 4; ni++) {
            int col = colBase + (wn << 5) + (ni << 3) + (t4 << 1);
            if (col < Ncols) {
                float bx = 0.f, by = 0.f;
                if (bias) { bx = bias[col]; by = bias[col + 1]; }
                float c00 = acc[mi][ni][0] + bx;
                float c01 = acc[mi][ni][1] + by;
                float c10 = acc[mi][ni][2] + bx;
                float c11 = acc[mi][ni][3] + by;
                if (orow0 >= 0) {
                    if (HALFC) {
                        __half2* cp = (__half2*)((__half*)Cv + (size_t)orow0 * Ncols + col);
                        *cp = __floats2half2_rn(c00, c01);
                    } else {
                        float* cp = (float*)Cv + (size_t)orow0 * Ncols + col;
                        cp[0] = c00;
                        cp[1] = c01;
                    }
                }
                if (orow1 >= 0) {
                    if (HALFC) {
                        __half2* cp = (__half2*)((__half*)Cv + (size_t)orow1 * Ncols + col);
                        *cp = __floats2half2_rn(c10, c11);
                    } else {
                        float* cp = (float*)Cv + (size_t)orow1 * Ncols + col;
                        cp[0] = c10;
                        cp[1] = c11;
                    }
                }
                if (asrc) {
                    float sx = __ldg(asrc + col), sy = __ldg(asrc + col + 1);
                    float dx = __ldg(adst + col), dy = __ldg(adst + col + 1);
                    es0 += c00 * sx + c01 * sy;
                    ed0 += c00 * dx + c01 * dy;
                    es1 += c10 * sx + c11 * sy;
                    ed1 += c10 * dx + c11 * dy;
                }
            }
        }
        if (asrc) {
            es0 += __shfl_xor_sync(0xffffffffu, es0, 1);
            es0 += __shfl_xor_sync(0xffffffffu, es0, 2);
            es1 += __shfl_xor_sync(0xffffffffu, es1, 1);
            es1 += __shfl_xor_sync(0xffffffffu, es1, 2);
            ed0 += __shfl_xor_sync(0xffffffffu, ed0, 1);
            ed0 += __shfl_xor_sync(0xffffffffu, ed0, 2);
            ed1 += __shfl_xor_sync(0xffffffffu, ed1, 1);
            ed1 += __shfl_xor_sync(0xffffffffu, ed1, 2);
            if (t4 == 0) {
                int head = (colBase + (wn << 5)) >> 6;
                if (orow0 >= 0) {
                    atomicAdd(&g_esed[(size_t)orow0 * HEADS + head], es0);
                    atomicAdd(&g_esed[ESZ + (size_t)orow0 * HEADS + head], ed0);
                }
                if (orow1 >= 0) {
                    atomicAdd(&g_esed[(size_t)orow1 * HEADS + head], es1);
                    atomicAdd(&g_esed[ESZ + (size_t)orow1 * HEADS + head], ed1);
                }
            }
        }
    }
}

// ---------------- fused softmax + aggregation, 4-wide edge batching: warp per (t, dst) ----------------
// out = ELU( (sum_e w_e * hp[src]) / (z + 1e-16) + bias ),  fp16 in (g_hph), fp16 out.
// 4 edges in flight per loop trip (MLP=4 on the gathers); tail masked via w=0.
__global__ void __launch_bounds__(256) agg_kernel(const float* __restrict__ bias,
                                                  __half* __restrict__ out)
{
    int gw = (blockIdx.x * 256 + threadIdx.x) >> 5;
    int lane = threadIdx.x & 31;
    if (gw >= TT * NN) return;
    int t = gw / NN;
    int d = gw - t * NN;
    int base = g_off[d];
    int deg = g_deg[d];
    const size_t tN = (size_t)t * NN;
    int myh = lane >> 3;                   // head of my 8 output cols
    float edh = __ldg(g_esed + ESZ + (size_t)gw * HEADS + myh);
    const __half* hpb = g_hph + tN * DD + lane * 8;
    const float* esb = g_esed + tN * HEADS + myh;

    float z = 0.f;
    float4 a0 = make_float4(0.f, 0.f, 0.f, 0.f);
    float4 a1 = make_float4(0.f, 0.f, 0.f, 0.f);
    for (int j0 = 0; j0 < deg; j0 += 4) {
        int rem = deg - j0;
        const int* sp = g_srcs + base + j0;
        int s0 = __ldg(sp);
        int s1 = (rem > 1) ? __ldg(sp + 1) : s0;
        int s2 = (rem > 2) ? __ldg(sp + 2) : s0;
        int s3 = (rem > 3) ? __ldg(sp + 3) : s0;
        // issue all es + gather loads before consuming (MLP=4)
        float e0 = __ldg(esb + (size_t)s0 * HEADS);
        float e1 = __ldg(esb + (size_t)s1 * HEADS);
        float e2 = __ldg(esb + (size_t)s2 * HEADS);
        float e3 = __ldg(esb + (size_t)s3 * HEADS);
        uint4 q0 = __ldg((const uint4*)(hpb + (size_t)s0 * DD));
        uint4 q1 = __ldg((const uint4*)(hpb + (size_t)s1 * DD));
        uint4 q2 = __ldg((const uint4*)(hpb + (size_t)s2 * DD));
        uint4 q3 = __ldg((const uint4*)(hpb + (size_t)s3 * DD));
        float v;
        v = e0 + edh; v = v > 0.f ? v : NEG_SLOPE * v;
        float w0 = __expf(v);
        v = e1 + edh; v = v > 0.f ? v : NEG_SLOPE * v;
        float w1 = (rem > 1) ? __expf(v) : 0.f;
        v = e2 + edh; v = v > 0.f ? v : NEG_SLOPE * v;
        float w2 = (rem > 2) ? __expf(v) : 0.f;
        v = e3 + edh; v = v > 0.f ? v : NEG_SLOPE * v;
        float w3 = (rem > 3) ? __expf(v) : 0.f;
        z += (w0 + w1) + (w2 + w3);
        {
            float2 f0 = __half22float2(*reinterpret_cast<const __half2*>(&q0.x));
            float2 f1 = __half22float2(*reinterpret_cast<const __half2*>(&q0.y));
            float2 f2 = __half22float2(*reinterpret_cast<const __half2*>(&q0.z));
            float2 f3 = __half22float2(*reinterpret_cast<const __half2*>(&q0.w));
            a0.x += w0 * f0.x; a0.y += w0 * f0.y;
            a0.z += w0 * f1.x; a0.w += w0 * f1.y;
            a1.x += w0 * f2.x; a1.y += w0 * f2.y;
            a1.z += w0 * f3.x; a1.w += w0 * f3.y;
        }
        {
            float2 f0 = __half22float2(*reinterpret_cast<const __half2*>(&q1.x));
            float2 f1 = __half22float2(*reinterpret_cast<const __half2*>(&q1.y));
            float2 f2 = __half22float2(*reinterpret_cast<const __half2*>(&q1.z));
            float2 f3 = __half22float2(*reinterpret_cast<const __half2*>(&q1.w));
            a0.x += w1 * f0.x; a0.y += w1 * f0.y;
            a0.z += w1 * f1.x; a0.w += w1 * f1.y;
            a1.x += w1 * f2.x; a1.y += w1 * f2.y;
            a1.z += w1 * f3.x; a1.w += w1 * f3.y;
        }
        {
            float2 f0 = __half22float2(*reinterpret_cast<const __half2*>(&q2.x));
            float2 f1 = __half22float2(*reinterpret_cast<const __half2*>(&q2.y));
            float2 f2 = __half22float2(*reinterpret_cast<const __half2*>(&q2.z));
            float2 f3 = __half22float2(*reinterpret_cast<const __half2*>(&q2.w));
            a0.x += w2 * f0.x; a0.y += w2 * f0.y;
            a0.z += w2 * f1.x; a0.w += w2 * f1.y;
            a1.x += w2 * f2.x; a1.y += w2 * f2.y;
            a1.z += w2 * f3.x; a1.w += w2 * f3.y;
        }
        {
            float2 f0 = __half22float2(*reinterpret_cast<const __half2*>(&q3.x));
            float2 f1 = __half22float2(*reinterpret_cast<const __half2*>(&q3.y));
            float2 f2 = __half22float2(*reinterpret_cast<const __half2*>(&q3.z));
            float2 f3 = __half22float2(*reinterpret_cast<const __half2*>(&q3.w));
            a0.x += w3 * f0.x; a0.y += w3 * f0.y;
            a0.z += w3 * f1.x; a0.w += w3 * f1.y;
            a1.x += w3 * f2.x; a1.y += w3 * f2.y;
            a1.z += w3 * f3.x; a1.w += w3 * f3.y;
        }
    }
    float zinv = 1.f / (z + 1e-16f);

    // ---- epilogue: normalize + bias + ELU, single fp16 write ----
    const float4* bp4 = (const float4*)bias + lane * 2;
    float4 b0v = __ldg(bp4), b1v = __ldg(bp4 + 1);
    uint4 o;
    __half2 h0o = __floats2half2_rn(eluf(a0.x * zinv + b0v.x), eluf(a0.y * zinv + b0v.y));
    __half2 h1o = __floats2half2_rn(eluf(a0.z * zinv + b0v.z), eluf(a0.w * zinv + b0v.w));
    __half2 h2o = __floats2half2_rn(eluf(a1.x * zinv + b1v.x), eluf(a1.y * zinv + b1v.y));
    __half2 h3o = __floats2half2_rn(eluf(a1.z * zinv + b1v.z), eluf(a1.w * zinv + b1v.w));
    o.x = *reinterpret_cast<uint32_t*>(&h0o);
    o.y = *reinterpret_cast<uint32_t*>(&h1o);
    o.z = *reinterpret_cast<uint32_t*>(&h2o);
    o.w = *reinterpret_cast<uint32_t*>(&h3o);
    *(uint4*)(out + (size_t)gw * DD + lane * 8) = o;
}

// ---------------- per-t column sums of embs (bufBh, fp16) ----------------
__global__ void __launch_bounds__(256) colsum_kernel()
{
    int t = blockIdx.y;
    int c = threadIdx.x;
    float s = 0.f;
    for (int n = blockIdx.x; n < NN; n += gridDim.x)
        s += __half2float(g_bufBh[((size_t)t * NN + n) * DD + c]);
    atomicAdd(&g_colsum[t * DD + c], s);
}

// ---------------- temporal attention weights (single block) ----------------
__global__ void __launch_bounds__(256) attn_kernel(
    const float* __restrict__ Wq, const float* __restrict__ bq,
    const float* __restrict__ Wk, const float* __restrict__ bk)
{
    __shared__ float mean[TT][DD];
    __shared__ float Kt[TT][DD];
    __shared__ float Qv[DD];
    __shared__ float red[256];
    __shared__ float sc[TT];
    int c = threadIdx.x;
#pragma unroll
    for (int t = 0; t < TT; t++)
        mean[t][c] = g_colsum[t * DD + c] * (1.0f / (float)NN);
    __syncthreads();
#pragma unroll
    for (int t = 0; t < TT; t++) {
        float acc = bk[c];
        for (int f = 0; f < DD; f++) acc += mean[t][f] * Wk[f * DD + c];
        Kt[t][c] = acc;
    }
    {
        float acc = bq[c];
        for (int f = 0; f < DD; f++) acc += mean[TT - 1][f] * Wq[f * DD + c];
        Qv[c] = acc;
    }
    __syncthreads();
    for (int t = 0; t < TT; t++) {
        red[c] = Qv[c] * Kt[t][c];
        __syncthreads();
        for (int off = 128; off > 0; off >>= 1) {
            if (c < off) red[c] += red[c + off];
            __syncthreads();
        }
        if (c == 0) sc[t] = red[0] * (1.0f / 16.0f);   // 1/sqrt(256)
        __syncthreads();
    }
    if (c == 0) {
        float m = fmaxf(fmaxf(sc[0], sc[1]), fmaxf(sc[2], sc[3]));
        float w0 = expf(sc[0] - m), w1 = expf(sc[1] - m);
        float w2 = expf(sc[2] - m), w3 = expf(sc[3] - m);
        float inv = 1.0f / (w0 + w1 + w2 + w3);
        g_attn[0] = w0 * inv; g_attn[1] = w1 * inv;
        g_attn[2] = w2 * inv; g_attn[3] = w3 * inv;
    }
}

// ---------------- launch ----------------
extern "C" void kernel_launch(void* const* d_in, const int* in_sizes, int n_in,
                              void* d_out, int out_size)
{
    const float* x      = (const float*)d_in[0];
    const int*   ei     = (const int*)  d_in[1];
    const float* Wp     = (const float*)d_in[2];
    const float* bp     = (const float*)d_in[3];
    const float* W0     = (const float*)d_in[4];
    const float* a_src0 = (const float*)d_in[5];
    const float* a_dst0 = (const float*)d_in[6];
    const float* b0     = (const float*)d_in[7];
    const float* W1     = (const float*)d_in[8];
    const float* a_src1 = (const float*)d_in[9];
    const float* a_dst1 = (const float*)d_in[10];
    const float* b1     = (const float*)d_in[11];
    const float* Wq     = (const float*)d_in[12];
    const float* bq     = (const float*)d_in[13];
    const float* Wk     = (const float*)d_in[14];
    const float* bk     = (const float*)d_in[15];
    const float* Wv     = (const float*)d_in[16];
    const float* bv     = (const float*)d_in[17];

    float *h0, *esed, *cs;
    __half *hph, *bufAh, *bufBh, *Wpt, *W0t, *W1t, *Wvt;
    int *degp;
    cudaGetSymbolAddress((void**)&h0,    g_h0);
    cudaGetSymbolAddress((void**)&hph,   g_hph);
    cudaGetSymbolAddress((void**)&bufAh, g_bufAh);
    cudaGetSymbolAddress((void**)&bufBh, g_bufBh);
    cudaGetSymbolAddress((void**)&esed,  g_esed);
    cudaGetSymbolAddress((void**)&cs,    g_colsum);
    cudaGetSymbolAddress((void**)&degp,  g_deg);
    cudaGetSymbolAddress((void**)&Wpt,   g_Wpt);
    cudaGetSymbolAddress((void**)&W0t,   g_W0t);
    cudaGetSymbolAddress((void**)&W1t,   g_W1t);
    cudaGetSymbolAddress((void**)&Wvt,   g_Wvt);

    const int rowsTN = TT * NN;            // 120000
    const int edges  = ETOT;               // 270000
    const int gy = (rowsTN + 127) / 128;   // 938
    const int esed4 = 2 * ESZ / 4;         // 480000
    const int wtot = FIN * HH + HH * DD + 2 * DD * DD;   // 163840

    // ---- CSR build (graph shared across t and both layers) ----
    zero_kernel<<<(NN / 4 + 255) / 256, 256>>>((float4*)degp, NN / 4);
    hist_kernel<<<(edges + 255) / 256, 256>>>(ei);
    scan1_kernel<<<NB_SCAN, 256>>>();
    scan2_kernel<<<1, 256>>>();
    scan3_kernel<<<NB_SCAN, 256>>>();
    scatter_kernel<<<(edges + 255) / 256, 256>>>(ei);

    // ---- fp16 transposed weights ----
    wprep_kernel<<<(wtot + 255) / 256, 256>>>(Wp, W0, W1, Wv);

    // ---- h0(t,n) = x[n,t] @ Wp + bp  (64-wide, bias folded here, perm output) ----
    gemm_f16<0, 0, 0><<<dim3(1, gy), 256>>>(x, Wpt, bp, h0, rowsTN, FIN, HH,
                                            TT, NN, nullptr, nullptr);

    // ---- GAT layer 0: hp = h0 @ W0 (K=64, fp16 out), es/ed fused ----
    zero_kernel<<<(esed4 + 255) / 256, 256>>>((float4*)esed, esed4);
    gemm_f16<0, 0, 1><<<dim3(2, gy), 256>>>(h0, W0t, nullptr, hph, rowsTN, HH, DD,
                                            0, 0, a_src0, a_dst0);
    agg_kernel<<<(rowsTN + 7) / 8, 256>>>(b0, bufAh);

    // ---- GAT layer 1 (fp16 A in, fp16 hp out) ----
    zero_kernel<<<(esed4 + 255) / 256, 256>>>((float4*)esed, esed4);
    gemm_f16<0, 1, 1><<<dim3(2, gy), 256>>>(bufAh, W1t, nullptr, hph, rowsTN, DD, DD,
                                            0, 0, a_src1, a_dst1);
    agg_kernel<<<(rowsTN + 7) / 8, 256>>>(b1, bufBh);

    // ---- temporal attention ----
    zero_kernel<<<1, 256>>>((float4*)cs, TT * DD / 4);
    colsum_kernel<<<dim3(128, TT), 256>>>();
    attn_kernel<<<1, 256>>>(Wq, bq, Wk, bk);

    // ---- out = (sum_t attn[t] * embs_t) @ Wv + bv  (blend fused, fp16 A) ----
    gemm_f16<1, 1, 0><<<dim3(2, (NN + 127) / 128), 256>>>(bufBh, Wvt, bv, (float*)d_out,
                                                          NN, DD, DD, 0, 0, nullptr, nullptr);
}

// round 17
// speedup vs baseline: 1.1382x; 1.1382x over previous
#include <cuda_runtime.h>
#include <cuda_fp16.h>
#include <math.h>
#include <stdint.h>

#define NN 30000
#define TT 4
#define FIN 256
#define HH 64
#define HEADS 4
#define DD 256
#define EE 240000
#define ETOT 270000            // EE + NN self loops
#define NEG_SLOPE 0.2f
#define NB_SCAN 118            // ceil(NN/256)
#define ESZ (TT * NN * HEADS)
#define CSB 128                // colsum partial blocks

// ---------------- scratch (device globals: allocation-free) ----------------
__device__ __align__(16) float  g_h0[TT * NN * HH];     // xWp output (incl bp), (t,n) order
__device__ __align__(16) __half g_hph[TT * NN * DD];    // per-layer hp = h @ W  (fp16)
__device__ __align__(16) __half g_bufAh[TT * NN * DD];  // layer0 output (post ELU, fp16)
__device__ __align__(16) __half g_bufBh[TT * NN * DD];  // layer1 output (embs, fp16)
__device__ __align__(16) float  g_esed[2 * ESZ];        // es at 0, ed at ESZ (direct stores, no pre-zero)
__device__ __align__(16) float  g_cspart[TT * CSB * DD];// colsum partials
__device__ float g_attn[TT];
// fp16 transposed weights: Wt[c][k] = W[k][c]
__device__ __align__(16) __half g_Wpt[HH * FIN];        // [64][256]
__device__ __align__(16) __half g_W0t[DD * HH];         // [256][64]
__device__ __align__(16) __half g_W1t[DD * DD];
__device__ __align__(16) __half g_Wvt[DD * DD];
// CSR
__device__ int g_deg[NN];
__device__ int g_off[NN];
__device__ int g_cursor[NN];
__device__ int g_part[256];
__device__ int g_srcs[ETOT];

// ---------------- utility ----------------
__global__ void zero_kernel(float4* __restrict__ p, int n4) {
    int i = blockIdx.x * blockDim.x + threadIdx.x;
    if (i < n4) p[i] = make_float4(0.f, 0.f, 0.f, 0.f);
}

__device__ __forceinline__ float eluf(float x) { return x > 0.f ? x : expm1f(x); }

// fp16 HMMA m16n8k16, fp32 accumulate. fp16 mantissa == tf32 mantissa (10 bits),
// so precision matches the tf32 path (measured 2.6-2.8e-4) while doubling MMA rate.
__device__ __forceinline__ void mma_f16(float* c, const uint32_t* a, const uint32_t* b) {
    asm volatile(
        "mma.sync.aligned.m16n8k16.row.col.f32.f16.f16.f32 "
        "{%0,%1,%2,%3}, {%4,%5,%6,%7}, {%8,%9}, {%0,%1,%2,%3};"
        : "+f"(c[0]), "+f"(c[1]), "+f"(c[2]), "+f"(c[3])
        : "r"(a[0]), "r"(a[1]), "r"(a[2]), "r"(a[3]), "r"(b[0]), "r"(b[1]));
}

// ---------------- weight prep: fp16 transpose Wt[c][k] = W[k][c] ----------------
__global__ void wprep_kernel(const float* __restrict__ Wp, const float* __restrict__ W0,
                             const float* __restrict__ W1, const float* __restrict__ Wv)
{
    int idx = blockIdx.x * 256 + threadIdx.x;
    if (idx < FIN * HH) {                       // Wp: [256][64] -> Wpt[64][256]
        int k = idx / HH, c = idx % HH;
        g_Wpt[c * FIN + k] = __float2half(Wp[idx]);
        return;
    }
    idx -= FIN * HH;
    if (idx < HH * DD) {                        // W0: [64][256] -> W0t[256][64]
        int k = idx / DD, c = idx % DD;
        g_W0t[c * HH + k] = __float2half(W0[idx]);
        return;
    }
    idx -= HH * DD;
    if (idx < DD * DD) {                        // W1
        int k = idx / DD, c = idx % DD;
        g_W1t[c * DD + k] = __float2half(W1[idx]);
        return;
    }
    idx -= DD * DD;
    if (idx < DD * DD) {                        // Wv
        int k = idx / DD, c = idx % DD;
        g_Wvt[c * DD + k] = __float2half(Wv[idx]);
    }
}

// ---------------- CSR build ----------------
__global__ void hist_kernel(const int* __restrict__ ei) {
    int e = blockIdx.x * 256 + threadIdx.x;
    if (e >= ETOT) return;
    int d = (e < EE) ? ei[EE + e] : (e - EE);
    atomicAdd(&g_deg[d], 1);
}

__global__ void scan1_kernel() {
    __shared__ int sh[256];
    int tid = threadIdx.x;
    int i = blockIdx.x * 256 + tid;
    int v = (i < NN) ? g_deg[i] : 0;
    sh[tid] = v;
    __syncthreads();
#pragma unroll
    for (int off = 1; off < 256; off <<= 1) {
        int t = (tid >= off) ? sh[tid - off] : 0;
        __syncthreads();
        sh[tid] += t;
        __syncthreads();
    }
    if (i < NN) g_off[i] = sh[tid] - v;       // exclusive (local)
    if (tid == 255) g_part[blockIdx.x] = sh[255];
}

__global__ void scan2_kernel() {
    __shared__ int sh[256];
    int tid = threadIdx.x;
    int v = (tid < NB_SCAN) ? g_part[tid] : 0;
    sh[tid] = v;
    __syncthreads();
#pragma unroll
    for (int off = 1; off < 256; off <<= 1) {
        int t = (tid >= off) ? sh[tid - off] : 0;
        __syncthreads();
        sh[tid] += t;
        __syncthreads();
    }
    if (tid < NB_SCAN) g_part[tid] = sh[tid] - v;  // exclusive
}

__global__ void scan3_kernel() {
    int i = blockIdx.x * 256 + threadIdx.x;
    if (i < NN) {
        int o = g_off[i] + g_part[blockIdx.x];
        g_off[i] = o;
        g_cursor[i] = o;
    }
}

__global__ void scatter_kernel(const int* __restrict__ ei) {
    int e = blockIdx.x * 256 + threadIdx.x;
    if (e >= ETOT) return;
    int s, d;
    if (e < EE) { s = ei[e]; d = ei[EE + e]; }
    else        { s = e - EE; d = s; }
    int pos = atomicAdd(&g_cursor[d], 1);
    g_srcs[pos] = s;
}

// ---------------- fp16 tensor-core GEMM, double-buffered, fused esed / blend ----------------
// C(R x Nc) = A(R x K) @ B(K x Nc) (+bias). 128x128 tile, KTILE=16, 256 threads.
// Bt is half, pre-transposed [Ncols][K]. K multiple of 16.
// permT!=0: output row r=(n*permT+t) -> t*permN+n.
// asrc/adst != null (requires permT==0): per-head dots of the BIASED output row are
//   reduced in SMEM and STORED directly to g_esed (no pre-zero, no global atomics) —
//   each (row, head) is owned by exactly one block.
// BLEND (requires AHALF): A row r = sum_t g_attn[t] * A[t*SLAB + r*K + k].
// AHALF: A is __half*.  HALFC: C is __half*.
template<int BLEND, int AHALF, int HALFC>
__global__ void __launch_bounds__(256) gemm_f16(
    const void* __restrict__ Av, const __half* __restrict__ Bt,
    const float* __restrict__ bias, void* __restrict__ Cv,
    int Rows, int K, int Ncols, int permT, int permN,
    const float* __restrict__ asrc, const float* __restrict__ adst)
{
    __shared__ __half Ash[2][128][24];   // [row][k], 16 used + 8 pad -> frag word row*12+t4, conflict-free
    __shared__ __half Bsh[2][128][24];   // [col][k]
    __shared__ float  sred[128][4];      // [row][head2*2 + {es,ed}]
    const int tid = threadIdx.x;
    const int wid = tid >> 5;
    const int lane = tid & 31;
    const int wm = wid >> 2;        // 0..1
    const int wn = wid & 3;         // 0..3
    const int g = lane >> 2;        // 0..7
    const int t4 = lane & 3;        // 0..3
    const int rowBase = blockIdx.y << 7;
    const int colBase = blockIdx.x << 7;

    const int arow = tid >> 1;            // 0..127 (also B col index)
    const int ak8 = (tid & 1) << 3;       // 0 / 8

    float acc[4][4][4];
#pragma unroll
    for (int mi = 0; mi < 4; mi++)
#pragma unroll
        for (int ni = 0; ni < 4; ni++)
#pragma unroll
            for (int q = 0; q < 4; q++) acc[mi][ni][q] = 0.f;

    const int gr = rowBase + arow;
    const bool aOK = gr < Rows;
    const size_t aoff = (size_t)(aOK ? gr : 0) * K + ak8;
    const float*  Apf = (const float*)Av + aoff;
    const __half* Aph = (const __half*)Av + aoff;
    const int gcol = colBase + arow;
    const bool bcOK = gcol < Ncols;
    const __half* Btp = Bt + (size_t)(bcOK ? gcol : 0) * K + ak8;
    const size_t SLAB = (size_t)NN * DD;

    float atw[4] = {0.f, 0.f, 0.f, 0.f};
    if (BLEND) { atw[0] = g_attn[0]; atw[1] = g_attn[1]; atw[2] = g_attn[2]; atw[3] = g_attn[3]; }

    const int nk = K >> 4;
    __half2 rah[4];
    uint4 rbh;

    auto load_tile = [&](int kt) {
        const int kb = kt << 4;
        if (AHALF && !BLEND) {
            uint4 q = make_uint4(0u, 0u, 0u, 0u);
            if (aOK) q = __ldg((const uint4*)(Aph + kb));
            *(uint4*)rah = q;
        } else if (AHALF && BLEND) {
            float v[8];
#pragma unroll
            for (int i = 0; i < 8; i++) v[i] = 0.f;
            if (aOK) {
#pragma unroll
                for (int s = 0; s < 4; s++) {
                    uint4 q = __ldg((const uint4*)(Aph + kb + s * SLAB));
                    float2 f0 = __half22float2(*reinterpret_cast<const __half2*>(&q.x));
                    float2 f1 = __half22float2(*reinterpret_cast<const __half2*>(&q.y));
                    float2 f2 = __half22float2(*reinterpret_cast<const __half2*>(&q.z));
                    float2 f3 = __half22float2(*reinterpret_cast<const __half2*>(&q.w));
                    v[0] += atw[s] * f0.x; v[1] += atw[s] * f0.y;
                    v[2] += atw[s] * f1.x; v[3] += atw[s] * f1.y;
                    v[4] += atw[s] * f2.x; v[5] += atw[s] * f2.y;
                    v[6] += atw[s] * f3.x; v[7] += atw[s] * f3.y;
                }
            }
            rah[0] = __floats2half2_rn(v[0], v[1]);
            rah[1] = __floats2half2_rn(v[2], v[3]);
            rah[2] = __floats2half2_rn(v[4], v[5]);
            rah[3] = __floats2half2_rn(v[6], v[7]);
        } else {
            float4 u0 = make_float4(0.f, 0.f, 0.f, 0.f);
            float4 u1 = u0;
            if (aOK) {
                u0 = *(const float4*)(Apf + kb);
                u1 = *(const float4*)(Apf + kb + 4);
            }
            rah[0] = __floats2half2_rn(u0.x, u0.y);
            rah[1] = __floats2half2_rn(u0.z, u0.w);
            rah[2] = __floats2half2_rn(u1.x, u1.y);
            rah[3] = __floats2half2_rn(u1.z, u1.w);
        }
        rbh = make_uint4(0u, 0u, 0u, 0u);
        if (bcOK) rbh = __ldg((const uint4*)(Btp + kb));
    };
    auto store_tile = [&](int buf) {
        *(uint4*)&Ash[buf][arow][ak8] = *(const uint4*)rah;
        *(uint4*)&Bsh[buf][arow][ak8] = rbh;
    };

    load_tile(0);
    store_tile(0);
    __syncthreads();

    for (int kt = 0; kt < nk; kt++) {
        const int buf = kt & 1;
        if (kt + 1 < nk) load_tile(kt + 1);
        const uint32_t* A32 = (const uint32_t*)&Ash[buf][0][0];
        const uint32_t* B32 = (const uint32_t*)&Bsh[buf][0][0];
        uint32_t afr[4][4];
        uint32_t bfr[4][2];
#pragma unroll
        for (int mi = 0; mi < 4; mi++) {
            int row = (wm << 6) + (mi << 4) + g;
            afr[mi][0] = A32[row * 12 + t4];
            afr[mi][1] = A32[(row + 8) * 12 + t4];
            afr[mi][2] = A32[row * 12 + t4 + 4];
            afr[mi][3] = A32[(row + 8) * 12 + t4 + 4];
        }
#pragma unroll
        for (int ni = 0; ni < 4; ni++) {
            int col = (wn << 5) + (ni << 3) + g;
            bfr[ni][0] = B32[col * 12 + t4];
            bfr[ni][1] = B32[col * 12 + t4 + 4];
        }
#pragma unroll
        for (int mi = 0; mi < 4; mi++)
#pragma unroll
            for (int ni = 0; ni < 4; ni++)
                mma_f16(acc[mi][ni], afr[mi], bfr[ni]);
        if (kt + 1 < nk) {
            store_tile(buf ^ 1);
            __syncthreads();
        }
    }

    // ---- esed smem buffer init (uniform branch: asrc is block-uniform) ----
    if (asrc) {
        ((float*)sred)[tid] = 0.f;
        ((float*)sred)[tid + 256] = 0.f;
        __syncthreads();
    }

    // ---- epilogue: bias -> C value, store C (fp32 or fp16), fused es/ed dots ----
#pragma unroll
    for (int mi = 0; mi < 4; mi++) {
        int lrow0 = (wm << 6) + (mi << 4) + g;
        int lrow1 = lrow0 + 8;
        int row0 = rowBase + lrow0;
        int row1 = rowBase + lrow1;
        int orow0 = -1, orow1 = -1;
        if (row0 < Rows) orow0 = permT ? ((row0 % permT) * permN + row0 / permT) : row0;
        if (row1 < Rows) orow1 = permT ? ((row1 % permT) * permN + row1 / permT) : row1;
        float es0 = 0.f, es1 = 0.f, ed0 = 0.f, ed1 = 0.f;
#pragma unroll
        for (int ni = 0; ni < 4; ni++) {
            int col = colBase + (wn << 5) + (ni << 3) + (t4 << 1);
            if (col < Ncols) {
                float bx = 0.f, by = 0.f;
                if (bias) { bx = bias[col]; by = bias[col + 1]; }
                float c00 = acc[mi][ni][0] + bx;
                float c01 = acc[mi][ni][1] + by;
                float c10 = acc[mi][ni][2] + bx;
                float c11 = acc[mi][ni][3] + by;
                if (orow0 >= 0) {
                    if (HALFC) {
                        __half2* cp = (__half2*)((__half*)Cv + (size_t)orow0 * Ncols + col);
                        *cp = __floats2half2_rn(c00, c01);
                    } else {
                        float* cp = (float*)Cv + (size_t)orow0 * Ncols + col;
                        cp[0] = c00;
                        cp[1] = c01;
                    }
                }
                if (orow1 >= 0) {
                    if (HALFC) {
                        __half2* cp = (__half2*)((__half*)Cv + (size_t)orow1 * Ncols + col);
                        *cp = __floats2half2_rn(c10, c11);
                    } else {
                        float* cp = (float*)Cv + (size_t)orow1 * Ncols + col;
                        cp[0] = c10;
                        cp[1] = c11;
                    }
                }
                if (asrc) {
                    float sx = __ldg(asrc + col), sy = __ldg(asrc + col + 1);
                    float dx = __ldg(adst + col), dy = __ldg(adst + col + 1);
                    es0 += c00 * sx + c01 * sy;
                    ed0 += c00 * dx + c01 * dy;
                    es1 += c10 * sx + c11 * sy;
                    ed1 += c10 * dx + c11 * dy;
                }
            }
        }
        if (asrc) {
            es0 += __shfl_xor_sync(0xffffffffu, es0, 1);
            es0 += __shfl_xor_sync(0xffffffffu, es0, 2);
            es1 += __shfl_xor_sync(0xffffffffu, es1, 1);
            es1 += __shfl_xor_sync(0xffffffffu, es1, 2);
            ed0 += __shfl_xor_sync(0xffffffffu, ed0, 1);
            ed0 += __shfl_xor_sync(0xffffffffu, ed0, 2);
            ed1 += __shfl_xor_sync(0xffffffffu, ed1, 1);
            ed1 += __shfl_xor_sync(0xffffffffu, ed1, 2);
            if (t4 == 0) {
                int h2 = wn >> 1;                 // head within block (0/1)
                atomicAdd(&sred[lrow0][h2 * 2 + 0], es0);
                atomicAdd(&sred[lrow0][h2 * 2 + 1], ed0);
                atomicAdd(&sred[lrow1][h2 * 2 + 0], es1);
                atomicAdd(&sred[lrow1][h2 * 2 + 1], ed1);
            }
        }
    }

    // ---- esed write-out: direct stores (one block owns each (row, head)) ----
    if (asrc) {
        __syncthreads();
        int headBase = colBase >> 6;
#pragma unroll
        for (int e = tid; e < 512; e += 256) {
            int row = e >> 2;
            int rest = e & 3;
            int grow = rowBase + row;
            if (grow < Rows) {
                int head = headBase + (rest >> 1);
                int isED = rest & 1;
                g_esed[(size_t)isED * ESZ + (size_t)grow * HEADS + head] = sred[row][(rest >> 1) * 2 + isED];
            }
        }
    }
}

// ---------------- fused softmax + aggregation, SINGLE PASS: warp per (t, dst) ----------------
// out = ELU( (sum_e w_e * hp[src]) / (z + 1e-16) + bias ),  fp16 in (g_hph), fp16 out.
__global__ void __launch_bounds__(256) agg_kernel(const float* __restrict__ bias,
                                                  __half* __restrict__ out)
{
    int gw = (blockIdx.x * 256 + threadIdx.x) >> 5;
    int lane = threadIdx.x & 31;
    if (gw >= TT * NN) return;
    int t = gw / NN;
    int d = gw - t * NN;
    int base = g_off[d];
    int deg = g_deg[d];
    const size_t tN = (size_t)t * NN;
    int myh = lane >> 3;                   // head of my 8 output cols
    float edh = __ldg(g_esed + ESZ + (size_t)gw * HEADS + myh);

    float z = 0.f;
    float4 a0 = make_float4(0.f, 0.f, 0.f, 0.f);
    float4 a1 = make_float4(0.f, 0.f, 0.f, 0.f);
    for (int j = 0; j < deg; j++) {
        int s = g_srcs[base + j];
        float es = __ldg(g_esed + (tN + s) * HEADS + myh);
        float v = es + edh;
        v = v > 0.f ? v : NEG_SLOPE * v;
        float w = __expf(v);
        z += w;
        const uint4 q = __ldg((const uint4*)(g_hph + (tN + s) * DD + lane * 8));
        float2 f0 = __half22float2(*reinterpret_cast<const __half2*>(&q.x));
        float2 f1 = __half22float2(*reinterpret_cast<const __half2*>(&q.y));
        float2 f2 = __half22float2(*reinterpret_cast<const __half2*>(&q.z));
        float2 f3 = __half22float2(*reinterpret_cast<const __half2*>(&q.w));
        a0.x += w * f0.x; a0.y += w * f0.y;
        a0.z += w * f1.x; a0.w += w * f1.y;
        a1.x += w * f2.x; a1.y += w * f2.y;
        a1.z += w * f3.x; a1.w += w * f3.y;
    }
    float zinv = 1.f / (z + 1e-16f);

    // ---- epilogue: normalize + bias + ELU, single fp16 write ----
    const float4* bp4 = (const float4*)bias + lane * 2;
    float4 b0v = __ldg(bp4), b1v = __ldg(bp4 + 1);
    uint4 o;
    __half2 h0o = __floats2half2_rn(eluf(a0.x * zinv + b0v.x), eluf(a0.y * zinv + b0v.y));
    __half2 h1o = __floats2half2_rn(eluf(a0.z * zinv + b0v.z), eluf(a0.w * zinv + b0v.w));
    __half2 h2o = __floats2half2_rn(eluf(a1.x * zinv + b1v.x), eluf(a1.y * zinv + b1v.y));
    __half2 h3o = __floats2half2_rn(eluf(a1.z * zinv + b1v.z), eluf(a1.w * zinv + b1v.w));
    o.x = *reinterpret_cast<uint32_t*>(&h0o);
    o.y = *reinterpret_cast<uint32_t*>(&h1o);
    o.z = *reinterpret_cast<uint32_t*>(&h2o);
    o.w = *reinterpret_cast<uint32_t*>(&h3o);
    *(uint4*)(out + (size_t)gw * DD + lane * 8) = o;
}

// ---------------- per-t column partial sums of embs (bufBh, fp16) -> g_cspart ----------------
__global__ void __launch_bounds__(256) colsum_kernel()
{
    int t = blockIdx.y;
    int b = blockIdx.x;
    int c = threadIdx.x;
    float s = 0.f;
    for (int n = b; n < NN; n += CSB)
        s += __half2float(g_bufBh[((size_t)t * NN + n) * DD + c]);
    g_cspart[((size_t)t * CSB + b) * DD + c] = s;
}

// ---------------- temporal attention weights (single block) ----------------
__global__ void __launch_bounds__(256) attn_kernel(
    const float* __restrict__ Wq, const float* __restrict__ bq,
    const float* __restrict__ Wk, const float* __restrict__ bk)
{
    __shared__ float mean[TT][DD];
    __shared__ float Kt[TT][DD];
    __shared__ float Qv[DD];
    __shared__ float red[256];
    __shared__ float sc[TT];
    int c = threadIdx.x;
#pragma unroll
    for (int t = 0; t < TT; t++) {
        float s = 0.f;
        for (int b = 0; b < CSB; b++)
            s += g_cspart[((size_t)t * CSB + b) * DD + c];
        mean[t][c] = s * (1.0f / (float)NN);
    }
    __syncthreads();
#pragma unroll
    for (int t = 0; t < TT; t++) {
        float acc = bk[c];
        for (int f = 0; f < DD; f++) acc += mean[t][f] * Wk[f * DD + c];
        Kt[t][c] = acc;
    }
    {
        float acc = bq[c];
        for (int f = 0; f < DD; f++) acc += mean[TT - 1][f] * Wq[f * DD + c];
        Qv[c] = acc;
    }
    __syncthreads();
    for (int t = 0; t < TT; t++) {
        red[c] = Qv[c] * Kt[t][c];
        __syncthreads();
        for (int off = 128; off > 0; off >>= 1) {
            if (c < off) red[c] += red[c + off];
            __syncthreads();
        }
        if (c == 0) sc[t] = red[0] * (1.0f / 16.0f);   // 1/sqrt(256)
        __syncthreads();
    }
    if (c == 0) {
        float m = fmaxf(fmaxf(sc[0], sc[1]), fmaxf(sc[2], sc[3]));
        float w0 = expf(sc[0] - m), w1 = expf(sc[1] - m);
        float w2 = expf(sc[2] - m), w3 = expf(sc[3] - m);
        float inv = 1.0f / (w0 + w1 + w2 + w3);
        g_attn[0] = w0 * inv; g_attn[1] = w1 * inv;
        g_attn[2] = w2 * inv; g_attn[3] = w3 * inv;
    }
}

// ---------------- launch ----------------
extern "C" void kernel_launch(void* const* d_in, const int* in_sizes, int n_in,
                              void* d_out, int out_size)
{
    const float* x      = (const float*)d_in[0];
    const int*   ei     = (const int*)  d_in[1];
    const float* Wp     = (const float*)d_in[2];
    const float* bp     = (const float*)d_in[3];
    const float* W0     = (const float*)d_in[4];
    const float* a_src0 = (const float*)d_in[5];
    const float* a_dst0 = (const float*)d_in[6];
    const float* b0     = (const float*)d_in[7];
    const float* W1     = (const float*)d_in[8];
    const float* a_src1 = (const float*)d_in[9];
    const float* a_dst1 = (const float*)d_in[10];
    const float* b1     = (const float*)d_in[11];
    const float* Wq     = (const float*)d_in[12];
    const float* bq     = (const float*)d_in[13];
    const float* Wk     = (const float*)d_in[14];
    const float* bk     = (const float*)d_in[15];
    const float* Wv     = (const float*)d_in[16];
    const float* bv     = (const float*)d_in[17];

    float *h0;
    __half *hph, *bufAh, *bufBh, *Wpt, *W0t, *W1t, *Wvt;
    int *degp;
    cudaGetSymbolAddress((void**)&h0,    g_h0);
    cudaGetSymbolAddress((void**)&hph,   g_hph);
    cudaGetSymbolAddress((void**)&bufAh, g_bufAh);
    cudaGetSymbolAddress((void**)&bufBh, g_bufBh);
    cudaGetSymbolAddress((void**)&degp,  g_deg);
    cudaGetSymbolAddress((void**)&Wpt,   g_Wpt);
    cudaGetSymbolAddress((void**)&W0t,   g_W0t);
    cudaGetSymbolAddress((void**)&W1t,   g_W1t);
    cudaGetSymbolAddress((void**)&Wvt,   g_Wvt);

    const int rowsTN = TT * NN;            // 120000
    const int edges  = ETOT;               // 270000
    const int gy = (rowsTN + 127) / 128;   // 938
    const int wtot = FIN * HH + HH * DD + 2 * DD * DD;   // 163840

    // ---- CSR build (graph shared across t and both layers) ----
    zero_kernel<<<(NN / 4 + 255) / 256, 256>>>((float4*)degp, NN / 4);
    hist_kernel<<<(edges + 255) / 256, 256>>>(ei);
    scan1_kernel<<<NB_SCAN, 256>>>();
    scan2_kernel<<<1, 256>>>();
    scan3_kernel<<<NB_SCAN, 256>>>();
    scatter_kernel<<<(edges + 255) / 256, 256>>>(ei);

    // ---- fp16 transposed weights ----
    wprep_kernel<<<(wtot + 255) / 256, 256>>>(Wp, W0, W1, Wv);

    // ---- h0(t,n) = x[n,t] @ Wp + bp  (64-wide, bias folded here, perm output) ----
    gemm_f16<0, 0, 0><<<dim3(1, gy), 256>>>(x, Wpt, bp, h0, rowsTN, FIN, HH,
                                            TT, NN, nullptr, nullptr);

    // ---- GAT layer 0: hp = h0 @ W0 (K=64, fp16 out), es/ed fused (direct store) ----
    gemm_f16<0, 0, 1><<<dim3(2, gy), 256>>>(h0, W0t, nullptr, hph, rowsTN, HH, DD,
                                            0, 0, a_src0, a_dst0);
    agg_kernel<<<(rowsTN + 7) / 8, 256>>>(b0, bufAh);

    // ---- GAT layer 1 (fp16 A in, fp16 hp out) ----
    gemm_f16<0, 1, 1><<<dim3(2, gy), 256>>>(bufAh, W1t, nullptr, hph, rowsTN, DD, DD,
                                            0, 0, a_src1, a_dst1);
    agg_kernel<<<(rowsTN + 7) / 8, 256>>>(b1, bufBh);

    // ---- temporal attention ----
    colsum_kernel<<<dim3(CSB, TT), 256>>>();
    attn_kernel<<<1, 256>>>(Wq, bq, Wk, bk);

    // ---- out = (sum_t attn[t] * embs_t) @ Wv + bv  (blend fused, fp16 A) ----
    gemm_f16<1, 1, 0><<<dim3(2, (NN + 127) / 128), 256>>>(bufBh, Wvt, bv, (float*)d_out,
                                                          NN, DD, DD, 0, 0, nullptr, nullptr);
}